// round 14
// baseline (speedup 1.0000x reference)
#include <cuda_runtime.h>
#include <math.h>

#define BB 32
#define CC 256
#define DD 128
#define NN 1024
#define EPS 1e-5f
#define SCALE 0.08838834764831843f  // 1/sqrt(128)

#define GST 20   // GEMM k-major smem row stride (words); %8==4 -> conflict-free ldsm

// ---------------- scratch (device globals; no allocations allowed) ----------
__device__ float g_q[2][BB * NN * DD];
__device__ float g_k[2][BB * NN * DD];
__device__ float g_v[2][BB * NN * CC];
__device__ float g_o[2][BB * NN * CC];
__device__ float g_part[64][16][2];   // per (seg, block) LN partial (sum, sumsq)

// ---------------- helpers ----------------------------------------------------
__device__ __forceinline__ unsigned f2tf(float f) {
    unsigned u;
    asm("cvt.rna.tf32.f32 %0, %1;" : "=r"(u) : "f"(f));
    return u;
}

__device__ __forceinline__ void mma8(float* c, const unsigned* a, const unsigned* b) {
    asm volatile(
        "mma.sync.aligned.m16n8k8.row.col.f32.tf32.tf32.f32 "
        "{%0,%1,%2,%3}, {%4,%5,%6,%7}, {%8,%9}, {%0,%1,%2,%3};"
        : "+f"(c[0]), "+f"(c[1]), "+f"(c[2]), "+f"(c[3])
        : "r"(a[0]), "r"(a[1]), "r"(a[2]), "r"(a[3]), "r"(b[0]), "r"(b[1]));
}

__device__ __forceinline__ void ldsm4(unsigned* r, const unsigned* p) {
    unsigned addr = (unsigned)__cvta_generic_to_shared(p);
    asm volatile("ldmatrix.sync.aligned.m8n8.x4.shared.b16 {%0,%1,%2,%3}, [%4];"
                 : "=r"(r[0]), "=r"(r[1]), "=r"(r[2]), "=r"(r[3]) : "r"(addr));
}

__device__ __forceinline__ void ldsm2(unsigned* r, const unsigned* p) {
    unsigned addr = (unsigned)__cvta_generic_to_shared(p);
    asm volatile("ldmatrix.sync.aligned.m8n8.x2.shared.b16 {%0,%1}, [%2];"
                 : "=r"(r[0]), "=r"(r[1]) : "r"(addr));
}

__device__ __forceinline__ void cpa16(void* dst, const void* src) {
    unsigned d = (unsigned)__cvta_generic_to_shared(dst);
    asm volatile("cp.async.ca.shared.global [%0], [%1], 16;" :: "r"(d), "l"(src));
}
#define CP_COMMIT() asm volatile("cp.async.commit_group;" ::: "memory")
#define CP_WAIT(n)  asm volatile("cp.async.wait_group %0;" :: "n"(n) : "memory")

// ---------------- GEMM loaders ------------------------------------------------
// transpose path: src[k][x] rows -> regs (coalesced)
__device__ __forceinline__ void ldg_kx(float4 v[2], const float* __restrict__ src,
                                       int ld, int k0, int x0, int t) {
    int row = t >> 4, col = (t & 15) * 4;
    const float* p = src + (size_t)(k0 + row) * ld + x0 + col;
    v[0] = *(const float4*)(p);
    v[1] = *(const float4*)(p + 64);
}
// scatter regs to S[x][k] k-major (raw fp32 bits; mma truncates to tf32)
__device__ __forceinline__ void sts_kx(unsigned* S, const float4 v[2], int t) {
    int k = t >> 4, x = (t & 15) * 4;
    S[(x + 0) * GST + k] = __float_as_uint(v[0].x);
    S[(x + 1) * GST + k] = __float_as_uint(v[0].y);
    S[(x + 2) * GST + k] = __float_as_uint(v[0].z);
    S[(x + 3) * GST + k] = __float_as_uint(v[0].w);
    S[(x + 64) * GST + k] = __float_as_uint(v[1].x);
    S[(x + 65) * GST + k] = __float_as_uint(v[1].y);
    S[(x + 66) * GST + k] = __float_as_uint(v[1].z);
    S[(x + 67) * GST + k] = __float_as_uint(v[1].w);
}
// direct path: src[x][k-contig] -> S[x][k] via cp.async (128 rows x 16 floats)
__device__ __forceinline__ void cpa_xk(unsigned* S, const float* __restrict__ src,
                                       int ld, int k0, int x0, int t) {
    int x = t >> 1, off = (t & 1) * 8;
    const float* p = src + (size_t)(x0 + x) * ld + k0 + off;
    cpa16(S + x * GST + off, p);
    cpa16(S + x * GST + off + 4, p + 4);
}

// ---------------- GEMM fragment compute: 128x128 block, BK=16, ldmatrix ------
__device__ __forceinline__ void gemm_frag(const unsigned* As, const unsigned* Bs,
                                          float acc[4][4][4], int wm, int wn, int lane) {
    const int lr15 = lane & 15, lkhi = (lane >> 4) * 4;
    const int brow = (lane & 7) + ((lane & 16) ? 8 : 0);
    const int bk   = (lane & 8) ? 4 : 0;
    const unsigned* bp0 = Bs + (wn * 32 + brow) * GST + bk;
    const unsigned* bp1 = bp0 + 16 * GST;
    const unsigned* ap  = As + (wm * 64 + lr15) * GST + lkhi;
#pragma unroll
    for (int kk = 0; kk < 16; kk += 8) {
        unsigned bf0[4], bf1[4];
        ldsm4(bf0, bp0 + kk);
        ldsm4(bf1, bp1 + kk);
#pragma unroll
        for (int mt = 0; mt < 4; mt++) {
            unsigned af[4];
            ldsm4(af, ap + mt * 16 * GST + kk);
            mma8(acc[mt][0], af, bf0);
            mma8(acc[mt][1], af, bf0 + 2);
            mma8(acc[mt][2], af, bf1);
            mma8(acc[mt][3], af, bf1 + 2);
        }
    }
}

// =============================================================================
// proj_all: all six projections in ONE launch. Y[b,n,d] = sum_c X[b,c,n] W[d,c]
// A (X) transpose via ldg+sts; B (W) direct via cp.async.
// =============================================================================
__global__ __launch_bounds__(256, 2)
void proj_all(const float* __restrict__ fs, const float* __restrict__ fi,
              const float* __restrict__ qs_w, const float* __restrict__ ks_w,
              const float* __restrict__ vs_w, const float* __restrict__ qi_w,
              const float* __restrict__ ki_w, const float* __restrict__ vi_w) {
    const int slot = blockIdx.y, dir = slot >> 2, s = slot & 3;
    const int b = blockIdx.z, n0 = blockIdx.x * 128;
    const float* X; const float* W; float* Y; int Dout, d0;
    if (s == 0)      { X = dir ? fs : fi; W = dir ? qs_w : qi_w; Y = g_q[dir]; Dout = DD; d0 = 0; }
    else if (s == 1) { X = dir ? fi : fs; W = dir ? ki_w : ks_w; Y = g_k[dir]; Dout = DD; d0 = 0; }
    else             { X = dir ? fi : fs; W = dir ? vi_w : vs_w; Y = g_v[dir]; Dout = CC; d0 = (s - 2) * 128; }

    __shared__ unsigned As[2][128 * GST], Bs[2][128 * GST];
    const float* Xb = X + (size_t)b * CC * NN;
    float* Yb = Y + (size_t)b * NN * Dout;
    const int t = threadIdx.x, lane = t & 31, w = t >> 5;
    const int wm = w >> 2, wn = w & 3;
    float acc[4][4][4] = {};
    float4 va[2];

    cpa_xk(Bs[0], W, CC, 0, d0, t);
    CP_COMMIT();
    ldg_kx(va, Xb, NN, 0, n0, t);
    sts_kx(As[0], va, t);
    CP_WAIT(0);
    __syncthreads();
    const int NIT = CC / 16;
    for (int it = 0; it < NIT; it++) {
        int buf = it & 1;
        if (it + 1 < NIT) {
            cpa_xk(Bs[buf ^ 1], W, CC, (it + 1) * 16, d0, t);
            CP_COMMIT();
            ldg_kx(va, Xb, NN, (it + 1) * 16, n0, t);
        }
        gemm_frag(As[buf], Bs[buf], acc, wm, wn, lane);
        if (it + 1 < NIT) {
            sts_kx(As[buf ^ 1], va, t);
            CP_WAIT(0);
            __syncthreads();
        }
    }
    const int r = lane >> 2, cq = lane & 3;
#pragma unroll
    for (int mt = 0; mt < 4; mt++) {
        int row = n0 + wm * 64 + mt * 16 + r;
#pragma unroll
        for (int nt = 0; nt < 4; nt++) {
            int col = d0 + wn * 32 + nt * 8 + cq * 2;
            *(float2*)(Yb + (size_t)row * Dout + col) =
                make_float2(acc[mt][nt][0], acc[mt][nt][1]);
            *(float2*)(Yb + (size_t)(row + 8) * Dout + col) =
                make_float2(acc[mt][nt][2], acc[mt][nt][3]);
        }
    }
}

// =============================================================================
// flash attention: occ-2, q-tile 64 / kv-tile 32, all fills cp.async.
// 256 threads = 8 warps (2m x 4n). smem ~94KB.
// =============================================================================
#define SQS 132
#define SKS 132
#define SVS 264
#define SPS 36
#define FO_Q 0
#define FO_K 8448
#define FO_V 12672
#define FO_P 21120
#define FO_M 23424   // sm_m[2][64] double-buffered
#define FO_L 23552
#define FO_RMAX 23616
#define FO_RSUM 23872
#define FL_WORDS 24128
#define FL_BYTES (FL_WORDS * 4)

__global__ __launch_bounds__(256, 2)
void flash_kernel() {
    extern __shared__ float sm[];
    unsigned* Sq  = (unsigned*)(sm + FO_Q);   // raw fp32 bits
    unsigned* Sk  = (unsigned*)(sm + FO_K);
    unsigned* Sv  = (unsigned*)(sm + FO_V);
    unsigned* Spu = (unsigned*)(sm + FO_P);
    float* sm_m = sm + FO_M;
    float* sm_l = sm + FO_L;
    float* rmax = sm + FO_RMAX;
    float* rsum = sm + FO_RSUM;

    const int z = blockIdx.y, dir = z >> 5, b = z & 31;
    const int q0 = blockIdx.x * 64;
    const float* Qg = g_q[dir] + (size_t)b * NN * DD + (size_t)q0 * DD;
    const float* Kg = g_k[dir] + (size_t)b * NN * DD;
    const float* Vg = g_v[dir] + (size_t)b * NN * CC;
    float* Og = g_o[dir] + (size_t)b * NN * CC;

    const int t = threadIdx.x, lane = t & 31, w = t >> 5;
    const int wm = w >> 2, wn = w & 3;
    const int r = lane >> 2, cq = lane & 3;

    const int lr15 = lane & 15;
    const int lkhi = (lane >> 4) * 4;
    const int bj   = lane & 7;
    const int bk   = (lane & 8) ? 4 : 0;

    // ---- Q tile 64x128 via cp.async (group 0) ----
    {
        int q = t >> 2;
#pragma unroll
        for (int i = 0; i < 8; i++) {
            int off = ((t & 3) + i * 4) * 4;
            cpa16(Sq + q * SQS + off, Qg + (size_t)q * DD + off);
        }
        CP_COMMIT();
    }
    if (t < 64) { sm_m[t] = -1e30f; sm_l[t] = 0.f; }

    float oacc[2][8][4] = {};
    const int R0 = wm * 32 + r;
    int cur = 0;

    for (int kt = 0; kt < NN / 32; kt++) {
        const int m0 = kt * 32;
        __syncthreads();   // A: prev iter done with Sk/Sv/Sp
        // ---- K tile 32x128 cp.async (committed FIRST) ----
        {
            int j = t >> 3;
#pragma unroll
            for (int i = 0; i < 4; i++) {
                int off = ((t & 7) + i * 8) * 4;
                cpa16(Sk + j * SKS + off, Kg + (size_t)(m0 + j) * DD + off);
            }
            CP_COMMIT();
        }
        // ---- V tile 32x256 cp.async (second group; drains before PV) ----
        {
            int c4 = t & 63, mb = t >> 6;
#pragma unroll
            for (int i = 0; i < 8; i++) {
                int m = mb + i * 4;
                cpa16(Sv + m * SVS + c4 * 4, Vg + (size_t)(m0 + m) * CC + c4 * 4);
            }
            CP_COMMIT();
        }
        CP_WAIT(1);        // Q (first iter) + K done; V may still fly
        __syncthreads();   // B: Sk ready

        // ---- S = Q Kt : warp tile 32(q) x 8(j) ----
        float sacc[2][4] = {};
        {
            const unsigned* ap0 = Sq + (wm * 32 + lr15) * SQS + lkhi;
            const unsigned* ap1 = ap0 + 16 * SQS;
            const unsigned* bp  = Sk + (wn * 8 + bj) * SKS + bk;
#pragma unroll
            for (int kk = 0; kk < DD; kk += 8) {
                unsigned a0[4], a1[4], bf[2];
                ldsm4(a0, ap0 + kk);
                ldsm4(a1, ap1 + kk);
                ldsm2(bf, bp + kk);
                mma8(sacc[0], a0, bf);
                mma8(sacc[1], a1, bf);
            }
        }

        // ---- row-max partials ----
        {
            float pm[4];
#pragma unroll
            for (int s = 0; s < 4; s++) {
                int mt = s >> 1, h = s & 1;
                pm[s] = fmaxf(sacc[mt][h * 2], sacc[mt][h * 2 + 1]) * SCALE;
            }
#pragma unroll
            for (int o = 1; o <= 2; o <<= 1)
#pragma unroll
                for (int s = 0; s < 4; s++)
                    pm[s] = fmaxf(pm[s], __shfl_xor_sync(0xffffffffu, pm[s], o));
            if (cq == 0) {
#pragma unroll
                for (int s = 0; s < 4; s++)
                    rmax[wn * 64 + R0 + s * 8] = pm[s];
            }
        }
        __syncthreads();   // C: rmax ready

        // ---- local stats ----
        float mnv[4], cloc[4];
#pragma unroll
        for (int s = 0; s < 4; s++) {
            int row = R0 + s * 8;
            float mo = sm_m[cur * 64 + row];
            float mn = fmaxf(fmaxf(rmax[row], rmax[64 + row]),
                             fmaxf(rmax[128 + row], rmax[192 + row]));
            mn = fmaxf(mo, mn);
            mnv[s] = mn;
            cloc[s] = __expf(mo - mn);
        }
        float cl_t = 0.f;
        if (t < 64) {
            float mo = sm_m[cur * 64 + t];
            float mn_t = fmaxf(fmaxf(rmax[t], rmax[64 + t]),
                               fmaxf(rmax[128 + t], rmax[192 + t]));
            mn_t = fmaxf(mo, mn_t);
            cl_t = __expf(mo - mn_t);
            sm_m[(cur ^ 1) * 64 + t] = mn_t;
        }

        // ---- exp in registers -> Sp[q][j] tf32; sum partials ----
        {
            float psum[4];
#pragma unroll
            for (int s = 0; s < 4; s++) {
                int mt = s >> 1, h = s & 1;
                int row = wm * 32 + mt * 16 + h * 8 + r;
                float p0 = __expf(sacc[mt][h * 2]     * SCALE - mnv[s]);
                float p1 = __expf(sacc[mt][h * 2 + 1] * SCALE - mnv[s]);
                psum[s] = p0 + p1;
                int col = wn * 8 + cq * 2;
                *(uint2*)&Spu[row * SPS + col] = make_uint2(f2tf(p0), f2tf(p1));
            }
#pragma unroll
            for (int o = 1; o <= 2; o <<= 1)
#pragma unroll
                for (int s = 0; s < 4; s++)
                    psum[s] += __shfl_xor_sync(0xffffffffu, psum[s], o);
            if (cq == 0) {
#pragma unroll
                for (int s = 0; s < 4; s++)
                    rsum[wn * 64 + R0 + s * 8] = psum[s];
            }
        }
        CP_WAIT(0);
        __syncthreads();   // D: Sp, rsum, Sv ready
        if (t < 64)
            sm_l[t] = sm_l[t] * cl_t + rsum[t] + rsum[64 + t]
                      + rsum[128 + t] + rsum[192 + t];

        // ---- rescale O ----
#pragma unroll
        for (int nt = 0; nt < 8; nt++) {
            oacc[0][nt][0] *= cloc[0]; oacc[0][nt][1] *= cloc[0];
            oacc[0][nt][2] *= cloc[1]; oacc[0][nt][3] *= cloc[1];
            oacc[1][nt][0] *= cloc[2]; oacc[1][nt][1] *= cloc[2];
            oacc[1][nt][2] *= cloc[3]; oacc[1][nt][3] *= cloc[3];
        }

        // ---- O += P V : warp tile 32(q) x 64(c), K=32 ----
        {
            const unsigned* pp0 = Spu + (wm * 32 + lr15) * SPS + lkhi;
            const unsigned* pp1 = pp0 + 16 * SPS;
#pragma unroll
            for (int kk = 0; kk < 32; kk += 8) {
                unsigned a0[4], a1[4], bf[8][2];
                ldsm4(a0, pp0 + kk);
                ldsm4(a1, pp1 + kk);
#pragma unroll
                for (int nt = 0; nt < 8; nt++) {
                    int nb = wn * 64 + nt * 8;
                    bf[nt][0] = Sv[(kk + cq) * SVS + nb + r];
                    bf[nt][1] = Sv[(kk + cq + 4) * SVS + nb + r];
                }
#pragma unroll
                for (int nt = 0; nt < 8; nt++) {
                    mma8(oacc[0][nt], a0, bf[nt]);
                    mma8(oacc[1][nt], a1, bf[nt]);
                }
            }
        }
        cur ^= 1;
    }
    __syncthreads();   // sm_l final

    // ---- epilogue: O / l -> g_o ----
    {
        float i0 = 1.f / sm_l[R0];
        float i1 = 1.f / sm_l[R0 + 8];
        float i2 = 1.f / sm_l[R0 + 16];
        float i3 = 1.f / sm_l[R0 + 24];
        int row0 = q0 + R0;
#pragma unroll
        for (int nt = 0; nt < 8; nt++) {
            int col = wn * 64 + nt * 8 + cq * 2;
            *(float2*)(Og + (size_t)row0 * CC + col) =
                make_float2(oacc[0][nt][0] * i0, oacc[0][nt][1] * i0);
            *(float2*)(Og + (size_t)(row0 + 8) * CC + col) =
                make_float2(oacc[0][nt][2] * i1, oacc[0][nt][3] * i1);
            *(float2*)(Og + (size_t)(row0 + 16) * CC + col) =
                make_float2(oacc[1][nt][0] * i2, oacc[1][nt][1] * i2);
            *(float2*)(Og + (size_t)(row0 + 24) * CC + col) =
                make_float2(oacc[1][nt][2] * i3, oacc[1][nt][3] * i3);
        }
    }
}

// =============================================================================
// fuse (transposed: M = c, N = n) + fused LN partial reduction.
// A (fw) + B2 (att) via cp.async; B1 (f) transpose via ldg+sts.
// =============================================================================
__global__ __launch_bounds__(256, 2)
void fuse_kernel(const float* __restrict__ fs, const float* __restrict__ fi,
                 const float* __restrict__ fw, const float* __restrict__ fbias,
                 float* __restrict__ outp) {
    __shared__ unsigned As[2][128 * GST], Bs[2][128 * GST];
    __shared__ float redS[8], redSS[8];
    const int z = blockIdx.z, dir = z >> 5, b = z & 31;
    const int n0 = blockIdx.x * 128, c0 = blockIdx.y * 128;
    const float* f = dir ? fi : fs;
    const float* fb = f + (size_t)b * CC * NN;
    const float* attb = g_o[dir] + (size_t)b * NN * CC;
    float* ob = outp + (size_t)z * CC * NN;
    const int t = threadIdx.x, lane = t & 31, w = t >> 5;
    const int wm = w >> 2, wn = w & 3;
    float acc[4][4][4] = {};
    float4 vb4[2];

    cpa_xk(As[0], fw, 2 * CC, 0, c0, t);
    CP_COMMIT();
    ldg_kx(vb4, fb, NN, 0, n0, t);
    sts_kx(Bs[0], vb4, t);
    CP_WAIT(0);
    __syncthreads();
    const int NIT = (2 * CC) / 16;
    for (int it = 0; it < NIT; it++) {
        int buf = it & 1;
        bool nxt_kx = false;
        if (it + 1 < NIT) {
            int k0 = (it + 1) * 16;
            cpa_xk(As[buf ^ 1], fw, 2 * CC, k0, c0, t);
            nxt_kx = (k0 < CC);
            if (nxt_kx) ldg_kx(vb4, fb, NN, k0, n0, t);
            else        cpa_xk(Bs[buf ^ 1], attb, CC, k0 - CC, n0, t);
            CP_COMMIT();
        }
        gemm_frag(As[buf], Bs[buf], acc, wm, wn, lane);
        if (it + 1 < NIT) {
            if (nxt_kx) sts_kx(Bs[buf ^ 1], vb4, t);
            CP_WAIT(0);
            __syncthreads();
        }
    }
    const int r = lane >> 2, cq = lane & 3;
    float ls = 0.f, lss = 0.f;
#pragma unroll
    for (int mt = 0; mt < 4; mt++) {
        int crow = c0 + wm * 64 + mt * 16 + r;
        float b0 = fbias[crow], b1 = fbias[crow + 8];
#pragma unroll
        for (int nt = 0; nt < 4; nt++) {
            int ncol = n0 + wn * 32 + nt * 8 + cq * 2;
            float2 r0 = *(const float2*)(fb + (size_t)crow * NN + ncol);
            float2 r1 = *(const float2*)(fb + (size_t)(crow + 8) * NN + ncol);
            float2 o0, o1;
            o0.x = fmaxf(acc[mt][nt][0] + b0, 0.f) + r0.x;
            o0.y = fmaxf(acc[mt][nt][1] + b0, 0.f) + r0.y;
            o1.x = fmaxf(acc[mt][nt][2] + b1, 0.f) + r1.x;
            o1.y = fmaxf(acc[mt][nt][3] + b1, 0.f) + r1.y;
            *(float2*)(ob + (size_t)crow * NN + ncol)       = o0;
            *(float2*)(ob + (size_t)(crow + 8) * NN + ncol) = o1;
            ls  += o0.x + o0.y + o1.x + o1.y;
            lss += o0.x * o0.x + o0.y * o0.y + o1.x * o1.x + o1.y * o1.y;
        }
    }
#pragma unroll
    for (int o = 16; o; o >>= 1) {
        ls  += __shfl_xor_sync(0xffffffffu, ls, o);
        lss += __shfl_xor_sync(0xffffffffu, lss, o);
    }
    if (lane == 0) { redS[w] = ls; redSS[w] = lss; }
    __syncthreads();
    if (t == 0) {
        float s = 0.f, ss = 0.f;
#pragma unroll
        for (int i = 0; i < 8; i++) { s += redS[i]; ss += redSS[i]; }
        int blk = blockIdx.y * 8 + blockIdx.x;
        g_part[z][blk][0] = s;
        g_part[z][blk][1] = ss;
    }
}

// =============================================================================
// ln_norm: each block recomputes its segment's stats from g_part (deterministic)
// grid (16 parts, 64 segs)
// =============================================================================
__global__ void ln_norm_kernel(float* __restrict__ outp,
                               const float* __restrict__ lnw_s, const float* __restrict__ lnb_s,
                               const float* __restrict__ lnw_i, const float* __restrict__ lnb_i) {
    const int seg = blockIdx.y, part = blockIdx.x;
    float s = 0.f, ss = 0.f;
#pragma unroll
    for (int i = 0; i < 16; i++) { s += g_part[seg][i][0]; ss += g_part[seg][i][1]; }
    const float inv_n = 1.0f / (CC * NN);
    const float mean = s * inv_n;
    const float rstd = rsqrtf(ss * inv_n - mean * mean + EPS);
    const bool isI = seg >= BB;
    const float* lw = isI ? lnw_i : lnw_s;
    const float* lb = isI ? lnb_i : lnb_s;
    float4* base = (float4*)(outp + (size_t)seg * CC * NN + part * 16384);
    for (int i = threadIdx.x; i < 4096; i += 256) {
        int c = part * 16 + (i >> 8);
        float wv = lw[c], bv = lb[c];
        float4 v = base[i];
        v.x = (v.x - mean) * rstd * wv + bv;
        v.y = (v.y - mean) * rstd * wv + bv;
        v.z = (v.z - mean) * rstd * wv + bv;
        v.w = (v.w - mean) * rstd * wv + bv;
        base[i] = v;
    }
}

// =============================================================================
extern "C" void kernel_launch(void* const* d_in, const int* in_sizes, int n_in,
                              void* d_out, int out_size) {
    const float* fs     = (const float*)d_in[0];
    const float* fi     = (const float*)d_in[1];
    const float* qs_w   = (const float*)d_in[2];
    const float* ks_w   = (const float*)d_in[3];
    const float* vs_w   = (const float*)d_in[4];
    const float* qi_w   = (const float*)d_in[5];
    const float* ki_w   = (const float*)d_in[6];
    const float* vi_w   = (const float*)d_in[7];
    const float* fuse_w = (const float*)d_in[8];
    const float* fuse_b = (const float*)d_in[9];
    const float* ln_s_w = (const float*)d_in[10];
    const float* ln_s_b = (const float*)d_in[11];
    const float* ln_i_w = (const float*)d_in[12];
    const float* ln_i_b = (const float*)d_in[13];
    float* out = (float*)d_out;

    cudaFuncSetAttribute(flash_kernel,
                         cudaFuncAttributeMaxDynamicSharedMemorySize, FL_BYTES);

    proj_all<<<dim3(8, 8, BB), 256>>>(fs, fi, qs_w, ks_w, vs_w, qi_w, ki_w, vi_w);

    flash_kernel<<<dim3(16, 64), 256, FL_BYTES>>>();

    fuse_kernel<<<dim3(8, 2, 64), 256>>>(fs, fi, fuse_w, fuse_b, out);

    ln_norm_kernel<<<dim3(16, 64), 256>>>(out, ln_s_w, ln_s_b, ln_i_w, ln_i_b);
}

// round 15
// speedup vs baseline: 1.4948x; 1.4948x over previous
#include <cuda_runtime.h>
#include <math.h>

#define BB 32
#define CC 256
#define DD 128
#define NN 1024
#define EPS 1e-5f
#define SCALE 0.08838834764831843f  // 1/sqrt(128)

#define GST 20   // GEMM k-major smem row stride (words); %8==4 -> conflict-free ldsm

// ---------------- scratch (device globals; no allocations allowed) ----------
__device__ float g_q[2][BB * NN * DD];
__device__ float g_k[2][BB * NN * DD];
__device__ float g_v[2][BB * NN * CC];
__device__ float g_o[2][BB * NN * CC];
__device__ float g_part[64][16][2];   // per (seg, block) LN partial (sum, sumsq)

// ---------------- helpers ----------------------------------------------------
__device__ __forceinline__ unsigned f2tf(float f) {
    unsigned u;
    asm("cvt.rna.tf32.f32 %0, %1;" : "=r"(u) : "f"(f));
    return u;
}

__device__ __forceinline__ void mma8(float* c, const unsigned* a, const unsigned* b) {
    asm volatile(
        "mma.sync.aligned.m16n8k8.row.col.f32.tf32.tf32.f32 "
        "{%0,%1,%2,%3}, {%4,%5,%6,%7}, {%8,%9}, {%0,%1,%2,%3};"
        : "+f"(c[0]), "+f"(c[1]), "+f"(c[2]), "+f"(c[3])
        : "r"(a[0]), "r"(a[1]), "r"(a[2]), "r"(a[3]), "r"(b[0]), "r"(b[1]));
}

__device__ __forceinline__ void ldsm4(unsigned* r, const unsigned* p) {
    unsigned addr = (unsigned)__cvta_generic_to_shared(p);
    asm volatile("ldmatrix.sync.aligned.m8n8.x4.shared.b16 {%0,%1,%2,%3}, [%4];"
                 : "=r"(r[0]), "=r"(r[1]), "=r"(r[2]), "=r"(r[3]) : "r"(addr));
}

__device__ __forceinline__ void ldsm2(unsigned* r, const unsigned* p) {
    unsigned addr = (unsigned)__cvta_generic_to_shared(p);
    asm volatile("ldmatrix.sync.aligned.m8n8.x2.shared.b16 {%0,%1}, [%2];"
                 : "=r"(r[0]), "=r"(r[1]) : "r"(addr));
}

__device__ __forceinline__ void cpa16(void* dst, const void* src) {
    unsigned d = (unsigned)__cvta_generic_to_shared(dst);
    asm volatile("cp.async.ca.shared.global [%0], [%1], 16;" :: "r"(d), "l"(src));
}
#define CP_COMMIT() asm volatile("cp.async.commit_group;" ::: "memory")
#define CP_WAIT(n)  asm volatile("cp.async.wait_group %0;" :: "n"(n) : "memory")

// ---------------- GEMM loaders ------------------------------------------------
// transpose path: src[k][x] rows -> regs (coalesced)
__device__ __forceinline__ void ldg_kx(float4 v[2], const float* __restrict__ src,
                                       int ld, int k0, int x0, int t) {
    int row = t >> 4, col = (t & 15) * 4;
    const float* p = src + (size_t)(k0 + row) * ld + x0 + col;
    v[0] = *(const float4*)(p);
    v[1] = *(const float4*)(p + 64);
}
// scatter regs to S[x][k] k-major (raw fp32 bits; mma truncates to tf32)
__device__ __forceinline__ void sts_kx(unsigned* S, const float4 v[2], int t) {
    int k = t >> 4, x = (t & 15) * 4;
    S[(x + 0) * GST + k] = __float_as_uint(v[0].x);
    S[(x + 1) * GST + k] = __float_as_uint(v[0].y);
    S[(x + 2) * GST + k] = __float_as_uint(v[0].z);
    S[(x + 3) * GST + k] = __float_as_uint(v[0].w);
    S[(x + 64) * GST + k] = __float_as_uint(v[1].x);
    S[(x + 65) * GST + k] = __float_as_uint(v[1].y);
    S[(x + 66) * GST + k] = __float_as_uint(v[1].z);
    S[(x + 67) * GST + k] = __float_as_uint(v[1].w);
}
// direct path: src[x][k-contig] -> S[x][k] via cp.async (128 rows x 16 floats)
__device__ __forceinline__ void cpa_xk(unsigned* S, const float* __restrict__ src,
                                       int ld, int k0, int x0, int t) {
    int x = t >> 1, off = (t & 1) * 8;
    const float* p = src + (size_t)(x0 + x) * ld + k0 + off;
    cpa16(S + x * GST + off, p);
    cpa16(S + x * GST + off + 4, p + 4);
}

// ---------------- GEMM fragment compute: 128x128 block, BK=16, ldmatrix ------
__device__ __forceinline__ void gemm_frag(const unsigned* As, const unsigned* Bs,
                                          float acc[4][4][4], int wm, int wn, int lane) {
    const int lr15 = lane & 15, lkhi = (lane >> 4) * 4;
    const int brow = (lane & 7) + ((lane & 16) ? 8 : 0);
    const int bk   = (lane & 8) ? 4 : 0;
    const unsigned* bp0 = Bs + (wn * 32 + brow) * GST + bk;
    const unsigned* bp1 = bp0 + 16 * GST;
    const unsigned* ap  = As + (wm * 64 + lr15) * GST + lkhi;
#pragma unroll
    for (int kk = 0; kk < 16; kk += 8) {
        unsigned bf0[4], bf1[4];
        ldsm4(bf0, bp0 + kk);
        ldsm4(bf1, bp1 + kk);
#pragma unroll
        for (int mt = 0; mt < 4; mt++) {
            unsigned af[4];
            ldsm4(af, ap + mt * 16 * GST + kk);
            mma8(acc[mt][0], af, bf0);
            mma8(acc[mt][1], af, bf0 + 2);
            mma8(acc[mt][2], af, bf1);
            mma8(acc[mt][3], af, bf1 + 2);
        }
    }
}

// =============================================================================
// proj_all: all six projections in ONE launch. Y[b,n,d] = sum_c X[b,c,n] W[d,c]
// =============================================================================
__global__ __launch_bounds__(256, 2)
void proj_all(const float* __restrict__ fs, const float* __restrict__ fi,
              const float* __restrict__ qs_w, const float* __restrict__ ks_w,
              const float* __restrict__ vs_w, const float* __restrict__ qi_w,
              const float* __restrict__ ki_w, const float* __restrict__ vi_w) {
    const int slot = blockIdx.y, dir = slot >> 2, s = slot & 3;
    const int b = blockIdx.z, n0 = blockIdx.x * 128;
    const float* X; const float* W; float* Y; int Dout, d0;
    if (s == 0)      { X = dir ? fs : fi; W = dir ? qs_w : qi_w; Y = g_q[dir]; Dout = DD; d0 = 0; }
    else if (s == 1) { X = dir ? fi : fs; W = dir ? ki_w : ks_w; Y = g_k[dir]; Dout = DD; d0 = 0; }
    else             { X = dir ? fi : fs; W = dir ? vi_w : vs_w; Y = g_v[dir]; Dout = CC; d0 = (s - 2) * 128; }

    __shared__ unsigned As[2][128 * GST], Bs[2][128 * GST];
    const float* Xb = X + (size_t)b * CC * NN;
    float* Yb = Y + (size_t)b * NN * Dout;
    const int t = threadIdx.x, lane = t & 31, w = t >> 5;
    const int wm = w >> 2, wn = w & 3;
    float acc[4][4][4] = {};
    float4 va[2];

    cpa_xk(Bs[0], W, CC, 0, d0, t);
    CP_COMMIT();
    ldg_kx(va, Xb, NN, 0, n0, t);
    sts_kx(As[0], va, t);
    CP_WAIT(0);
    __syncthreads();
    const int NIT = CC / 16;
    for (int it = 0; it < NIT; it++) {
        int buf = it & 1;
        if (it + 1 < NIT) {
            cpa_xk(Bs[buf ^ 1], W, CC, (it + 1) * 16, d0, t);
            CP_COMMIT();
            ldg_kx(va, Xb, NN, (it + 1) * 16, n0, t);
        }
        gemm_frag(As[buf], Bs[buf], acc, wm, wn, lane);
        if (it + 1 < NIT) {
            sts_kx(As[buf ^ 1], va, t);
            CP_WAIT(0);
            __syncthreads();
        }
    }
    const int r = lane >> 2, cq = lane & 3;
#pragma unroll
    for (int mt = 0; mt < 4; mt++) {
        int row = n0 + wm * 64 + mt * 16 + r;
#pragma unroll
        for (int nt = 0; nt < 4; nt++) {
            int col = d0 + wn * 32 + nt * 8 + cq * 2;
            *(float2*)(Yb + (size_t)row * Dout + col) =
                make_float2(acc[mt][nt][0], acc[mt][nt][1]);
            *(float2*)(Yb + (size_t)(row + 8) * Dout + col) =
                make_float2(acc[mt][nt][2], acc[mt][nt][3]);
        }
    }
}

// =============================================================================
// flash attention: R8 structure (proven) + K-prefetch-after-barrier-C.
// occ-2, q-tile 64 / kv-tile 32, 256 threads = 8 warps (2m x 4n).
// =============================================================================
#define SQS 132
#define SKS 132
#define SVS 264
#define SPS 36
#define FO_Q 0
#define FO_K 8448
#define FO_V 12672
#define FO_P 21120
#define FO_M 23424   // sm_m[2][64] double-buffered
#define FO_L 23552
#define FO_RMAX 23616
#define FO_RSUM 23872
#define FL_WORDS 24128
#define FL_BYTES (FL_WORDS * 4)

__global__ __launch_bounds__(256, 2)
void flash_kernel() {
    extern __shared__ float sm[];
    unsigned* Sq  = (unsigned*)(sm + FO_Q);   // tf32 (rounded)
    unsigned* Sk  = (unsigned*)(sm + FO_K);   // raw fp32 bits via cp.async
    unsigned* Sv  = (unsigned*)(sm + FO_V);   // raw fp32 bits via cp.async
    unsigned* Spu = (unsigned*)(sm + FO_P);   // tf32
    float* sm_m = sm + FO_M;
    float* sm_l = sm + FO_L;
    float* rmax = sm + FO_RMAX;
    float* rsum = sm + FO_RSUM;

    const int z = blockIdx.y, dir = z >> 5, b = z & 31;
    const int q0 = blockIdx.x * 64;
    const float* Qg = g_q[dir] + (size_t)b * NN * DD + (size_t)q0 * DD;
    const float* Kg = g_k[dir] + (size_t)b * NN * DD;
    const float* Vg = g_v[dir] + (size_t)b * NN * CC;
    float* Og = g_o[dir] + (size_t)b * NN * CC;

    const int t = threadIdx.x, lane = t & 31, w = t >> 5;
    const int wm = w >> 2, wn = w & 3;
    const int r = lane >> 2, cq = lane & 3;

    const int lr15 = lane & 15;
    const int lkhi = (lane >> 4) * 4;
    const int bj   = lane & 7;
    const int bk   = (lane & 8) ? 4 : 0;

    // ---- fill Sq[q][k]: 64 x 128 (LDG + cvt + STS; proven path) ----
    {
        int q = t >> 2, kg = (t & 3) * 4;
#pragma unroll
        for (int i = 0; i < 8; i++) {
            int k = kg + i * 16;
            float4 v = *(const float4*)(Qg + (size_t)q * DD + k);
            unsigned* p = Sq + q * SQS + k;
            p[0] = f2tf(v.x); p[1] = f2tf(v.y); p[2] = f2tf(v.z); p[3] = f2tf(v.w);
        }
    }
    if (t < 64) { sm_m[t] = -1e30f; sm_l[t] = 0.f; }

    float oacc[2][8][4] = {};
    const int R0 = wm * 32 + r;
    int cur = 0;
    const int NIT = NN / 32;

    // K fill lane mapping (reused for prefetch)
    const int kj = t >> 3, koff = (t & 7) * 4;

    for (int kt = 0; kt < NIT; kt++) {
        const int m0 = kt * 32;
        __syncthreads();   // A: prev iter done with Sv/Sp (Sk refilled after prev C)
        if (kt == 0) {
            // ---- K tile 32x128 cp.async (group committed BEFORE V) ----
#pragma unroll
            for (int i = 0; i < 4; i++) {
                int off = koff + i * 32;
                cpa16(Sk + kj * SKS + off, Kg + (size_t)kj * DD + off);
            }
            CP_COMMIT();
        }
        // ---- V tile 32x256 cp.async ----
        {
            int c4 = t & 63, mb = t >> 6;
#pragma unroll
            for (int i = 0; i < 8; i++) {
                int m = mb + i * 4;
                cpa16(Sv + m * SVS + c4 * 4, Vg + (size_t)(m0 + m) * CC + c4 * 4);
            }
            CP_COMMIT();
        }
        CP_WAIT(1);        // K_kt landed; V_kt still in flight
        __syncthreads();   // B: Sk ready

        // ---- S = Q Kt : warp tile 32(q) x 8(j) ----
        float sacc[2][4] = {};
        {
            const unsigned* ap0 = Sq + (wm * 32 + lr15) * SQS + lkhi;
            const unsigned* ap1 = ap0 + 16 * SQS;
            const unsigned* bp  = Sk + (wn * 8 + bj) * SKS + bk;
#pragma unroll
            for (int kk = 0; kk < DD; kk += 8) {
                unsigned a0[4], a1[4], bf[2];
                ldsm4(a0, ap0 + kk);
                ldsm4(a1, ap1 + kk);
                ldsm2(bf, bp + kk);
                mma8(sacc[0], a0, bf);
                mma8(sacc[1], a1, bf);
            }
        }

        // ---- row-max partials ----
        {
            float pm[4];
#pragma unroll
            for (int s = 0; s < 4; s++) {
                int mt = s >> 1, h = s & 1;
                pm[s] = fmaxf(sacc[mt][h * 2], sacc[mt][h * 2 + 1]) * SCALE;
            }
#pragma unroll
            for (int o = 1; o <= 2; o <<= 1)
#pragma unroll
                for (int s = 0; s < 4; s++)
                    pm[s] = fmaxf(pm[s], __shfl_xor_sync(0xffffffffu, pm[s], o));
            if (cq == 0) {
#pragma unroll
                for (int s = 0; s < 4; s++)
                    rmax[wn * 64 + R0 + s * 8] = pm[s];
            }
        }
        __syncthreads();   // C: rmax ready; Sk now dead (QK finished in all warps)

        // ---- PREFETCH K for next iter into Sk (overlaps softmax + PV) ----
        {
            const int mn = ((kt + 1) == NIT ? 0 : (kt + 1)) * 32;  // wrap: dummy, keeps group count uniform
#pragma unroll
            for (int i = 0; i < 4; i++) {
                int off = koff + i * 32;
                cpa16(Sk + kj * SKS + off, Kg + (size_t)(mn + kj) * DD + off);
            }
            CP_COMMIT();
        }

        // ---- local stats ----
        float mnv[4], cloc[4];
#pragma unroll
        for (int s = 0; s < 4; s++) {
            int row = R0 + s * 8;
            float mo = sm_m[cur * 64 + row];
            float mn = fmaxf(fmaxf(rmax[row], rmax[64 + row]),
                             fmaxf(rmax[128 + row], rmax[192 + row]));
            mn = fmaxf(mo, mn);
            mnv[s] = mn;
            cloc[s] = __expf(mo - mn);
        }
        float cl_t = 0.f;
        if (t < 64) {
            float mo = sm_m[cur * 64 + t];
            float mn_t = fmaxf(fmaxf(rmax[t], rmax[64 + t]),
                               fmaxf(rmax[128 + t], rmax[192 + t]));
            mn_t = fmaxf(mo, mn_t);
            cl_t = __expf(mo - mn_t);
            sm_m[(cur ^ 1) * 64 + t] = mn_t;
        }

        // ---- exp in registers -> Sp[q][j] tf32; sum partials ----
        {
            float psum[4];
#pragma unroll
            for (int s = 0; s < 4; s++) {
                int mt = s >> 1, h = s & 1;
                int row = wm * 32 + mt * 16 + h * 8 + r;
                float p0 = __expf(sacc[mt][h * 2]     * SCALE - mnv[s]);
                float p1 = __expf(sacc[mt][h * 2 + 1] * SCALE - mnv[s]);
                psum[s] = p0 + p1;
                int col = wn * 8 + cq * 2;
                *(uint2*)&Spu[row * SPS + col] = make_uint2(f2tf(p0), f2tf(p1));
            }
#pragma unroll
            for (int o = 1; o <= 2; o <<= 1)
#pragma unroll
                for (int s = 0; s < 4; s++)
                    psum[s] += __shfl_xor_sync(0xffffffffu, psum[s], o);
            if (cq == 0) {
#pragma unroll
                for (int s = 0; s < 4; s++)
                    rsum[wn * 64 + R0 + s * 8] = psum[s];
            }
        }
        CP_WAIT(1);        // V_kt landed; K-prefetch still in flight
        __syncthreads();   // D: Sp, rsum, Sv ready
        if (t < 64)
            sm_l[t] = sm_l[t] * cl_t + rsum[t] + rsum[64 + t]
                      + rsum[128 + t] + rsum[192 + t];

        // ---- rescale O ----
#pragma unroll
        for (int nt = 0; nt < 8; nt++) {
            oacc[0][nt][0] *= cloc[0]; oacc[0][nt][1] *= cloc[0];
            oacc[0][nt][2] *= cloc[1]; oacc[0][nt][3] *= cloc[1];
            oacc[1][nt][0] *= cloc[2]; oacc[1][nt][1] *= cloc[2];
            oacc[1][nt][2] *= cloc[3]; oacc[1][nt][3] *= cloc[3];
        }

        // ---- O += P V : warp tile 32(q) x 64(c), K=32 ----
        {
            const unsigned* pp0 = Spu + (wm * 32 + lr15) * SPS + lkhi;
            const unsigned* pp1 = pp0 + 16 * SPS;
#pragma unroll
            for (int kk = 0; kk < 32; kk += 8) {
                unsigned a0[4], a1[4], bf[8][2];
                ldsm4(a0, pp0 + kk);
                ldsm4(a1, pp1 + kk);
#pragma unroll
                for (int nt = 0; nt < 8; nt++) {
                    int nb = wn * 64 + nt * 8;
                    bf[nt][0] = f2tf(__uint_as_float(Sv[(kk + cq) * SVS + nb + r]));
                    bf[nt][1] = f2tf(__uint_as_float(Sv[(kk + cq + 4) * SVS + nb + r]));
                }
#pragma unroll
                for (int nt = 0; nt < 8; nt++) {
                    mma8(oacc[0][nt], a0, bf[nt]);
                    mma8(oacc[1][nt], a1, bf[nt]);
                }
            }
        }
        cur ^= 1;
    }
    CP_WAIT(0);        // drain trailing K-prefetch before exit
    __syncthreads();   // sm_l final

    // ---- epilogue: O / l -> g_o ----
    {
        float i0 = 1.f / sm_l[R0];
        float i1 = 1.f / sm_l[R0 + 8];
        float i2 = 1.f / sm_l[R0 + 16];
        float i3 = 1.f / sm_l[R0 + 24];
        int row0 = q0 + R0;
#pragma unroll
        for (int nt = 0; nt < 8; nt++) {
            int col = wn * 64 + nt * 8 + cq * 2;
            *(float2*)(Og + (size_t)row0 * CC + col) =
                make_float2(oacc[0][nt][0] * i0, oacc[0][nt][1] * i0);
            *(float2*)(Og + (size_t)(row0 + 8) * CC + col) =
                make_float2(oacc[0][nt][2] * i1, oacc[0][nt][3] * i1);
            *(float2*)(Og + (size_t)(row0 + 16) * CC + col) =
                make_float2(oacc[1][nt][0] * i2, oacc[1][nt][1] * i2);
            *(float2*)(Og + (size_t)(row0 + 24) * CC + col) =
                make_float2(oacc[1][nt][2] * i3, oacc[1][nt][3] * i3);
        }
    }
}

// =============================================================================
// fuse (transposed: M = c, N = n) + fused LN partial reduction.
// =============================================================================
__global__ __launch_bounds__(256, 2)
void fuse_kernel(const float* __restrict__ fs, const float* __restrict__ fi,
                 const float* __restrict__ fw, const float* __restrict__ fbias,
                 float* __restrict__ outp) {
    __shared__ unsigned As[2][128 * GST], Bs[2][128 * GST];
    __shared__ float redS[8], redSS[8];
    const int z = blockIdx.z, dir = z >> 5, b = z & 31;
    const int n0 = blockIdx.x * 128, c0 = blockIdx.y * 128;
    const float* f = dir ? fi : fs;
    const float* fb = f + (size_t)b * CC * NN;
    const float* attb = g_o[dir] + (size_t)b * NN * CC;
    float* ob = outp + (size_t)z * CC * NN;
    const int t = threadIdx.x, lane = t & 31, w = t >> 5;
    const int wm = w >> 2, wn = w & 3;
    float acc[4][4][4] = {};
    float4 vb4[2];

    cpa_xk(As[0], fw, 2 * CC, 0, c0, t);
    CP_COMMIT();
    ldg_kx(vb4, fb, NN, 0, n0, t);
    sts_kx(Bs[0], vb4, t);
    CP_WAIT(0);
    __syncthreads();
    const int NIT = (2 * CC) / 16;
    for (int it = 0; it < NIT; it++) {
        int buf = it & 1;
        bool nxt_kx = false;
        if (it + 1 < NIT) {
            int k0 = (it + 1) * 16;
            cpa_xk(As[buf ^ 1], fw, 2 * CC, k0, c0, t);
            nxt_kx = (k0 < CC);
            if (nxt_kx) ldg_kx(vb4, fb, NN, k0, n0, t);
            else        cpa_xk(Bs[buf ^ 1], attb, CC, k0 - CC, n0, t);
            CP_COMMIT();
        }
        gemm_frag(As[buf], Bs[buf], acc, wm, wn, lane);
        if (it + 1 < NIT) {
            if (nxt_kx) sts_kx(Bs[buf ^ 1], vb4, t);
            CP_WAIT(0);
            __syncthreads();
        }
    }
    const int r = lane >> 2, cq = lane & 3;
    float ls = 0.f, lss = 0.f;
#pragma unroll
    for (int mt = 0; mt < 4; mt++) {
        int crow = c0 + wm * 64 + mt * 16 + r;
        float b0 = fbias[crow], b1 = fbias[crow + 8];
#pragma unroll
        for (int nt = 0; nt < 4; nt++) {
            int ncol = n0 + wn * 32 + nt * 8 + cq * 2;
            float2 r0 = *(const float2*)(fb + (size_t)crow * NN + ncol);
            float2 r1 = *(const float2*)(fb + (size_t)(crow + 8) * NN + ncol);
            float2 o0, o1;
            o0.x = fmaxf(acc[mt][nt][0] + b0, 0.f) + r0.x;
            o0.y = fmaxf(acc[mt][nt][1] + b0, 0.f) + r0.y;
            o1.x = fmaxf(acc[mt][nt][2] + b1, 0.f) + r1.x;
            o1.y = fmaxf(acc[mt][nt][3] + b1, 0.f) + r1.y;
            *(float2*)(ob + (size_t)crow * NN + ncol)       = o0;
            *(float2*)(ob + (size_t)(crow + 8) * NN + ncol) = o1;
            ls  += o0.x + o0.y + o1.x + o1.y;
            lss += o0.x * o0.x + o0.y * o0.y + o1.x * o1.x + o1.y * o1.y;
        }
    }
#pragma unroll
    for (int o = 16; o; o >>= 1) {
        ls  += __shfl_xor_sync(0xffffffffu, ls, o);
        lss += __shfl_xor_sync(0xffffffffu, lss, o);
    }
    if (lane == 0) { redS[w] = ls; redSS[w] = lss; }
    __syncthreads();
    if (t == 0) {
        float s = 0.f, ss = 0.f;
#pragma unroll
        for (int i = 0; i < 8; i++) { s += redS[i]; ss += redSS[i]; }
        int blk = blockIdx.y * 8 + blockIdx.x;
        g_part[z][blk][0] = s;
        g_part[z][blk][1] = ss;
    }
}

// =============================================================================
// ln_norm: each block recomputes its segment's stats from g_part (deterministic)
// =============================================================================
__global__ void ln_norm_kernel(float* __restrict__ outp,
                               const float* __restrict__ lnw_s, const float* __restrict__ lnb_s,
                               const float* __restrict__ lnw_i, const float* __restrict__ lnb_i) {
    const int seg = blockIdx.y, part = blockIdx.x;
    float s = 0.f, ss = 0.f;
#pragma unroll
    for (int i = 0; i < 16; i++) { s += g_part[seg][i][0]; ss += g_part[seg][i][1]; }
    const float inv_n = 1.0f / (CC * NN);
    const float mean = s * inv_n;
    const float rstd = rsqrtf(ss * inv_n - mean * mean + EPS);
    const bool isI = seg >= BB;
    const float* lw = isI ? lnw_i : lnw_s;
    const float* lb = isI ? lnb_i : lnb_s;
    float4* base = (float4*)(outp + (size_t)seg * CC * NN + part * 16384);
    for (int i = threadIdx.x; i < 4096; i += 256) {
        int c = part * 16 + (i >> 8);
        float wv = lw[c], bv = lb[c];
        float4 v = base[i];
        v.x = (v.x - mean) * rstd * wv + bv;
        v.y = (v.y - mean) * rstd * wv + bv;
        v.z = (v.z - mean) * rstd * wv + bv;
        v.w = (v.w - mean) * rstd * wv + bv;
        base[i] = v;
    }
}

// =============================================================================
extern "C" void kernel_launch(void* const* d_in, const int* in_sizes, int n_in,
                              void* d_out, int out_size) {
    const float* fs     = (const float*)d_in[0];
    const float* fi     = (const float*)d_in[1];
    const float* qs_w   = (const float*)d_in[2];
    const float* ks_w   = (const float*)d_in[3];
    const float* vs_w   = (const float*)d_in[4];
    const float* qi_w   = (const float*)d_in[5];
    const float* ki_w   = (const float*)d_in[6];
    const float* vi_w   = (const float*)d_in[7];
    const float* fuse_w = (const float*)d_in[8];
    const float* fuse_b = (const float*)d_in[9];
    const float* ln_s_w = (const float*)d_in[10];
    const float* ln_s_b = (const float*)d_in[11];
    const float* ln_i_w = (const float*)d_in[12];
    const float* ln_i_b = (const float*)d_in[13];
    float* out = (float*)d_out;

    cudaFuncSetAttribute(flash_kernel,
                         cudaFuncAttributeMaxDynamicSharedMemorySize, FL_BYTES);

    proj_all<<<dim3(8, 8, BB), 256>>>(fs, fi, qs_w, ks_w, vs_w, qi_w, ki_w, vi_w);

    flash_kernel<<<dim3(16, 64), 256, FL_BYTES>>>();

    fuse_kernel<<<dim3(8, 2, 64), 256>>>(fs, fi, fuse_w, fuse_b, out);

    ln_norm_kernel<<<dim3(16, 64), 256>>>(out, ln_s_w, ln_s_b, ln_i_w, ln_i_b);
}

// round 17
// speedup vs baseline: 1.5654x; 1.0473x over previous
#include <cuda_runtime.h>
#include <math.h>

#define BB 32
#define CC 256
#define DD 128
#define NN 1024
#define EPS 1e-5f
#define SCALE 0.08838834764831843f  // 1/sqrt(128)

#define GST 20   // GEMM k-major smem row stride (words); %8==4 -> conflict-free ldsm

// ---------------- scratch (device globals; no allocations allowed) ----------
__device__ float g_q[2][BB * NN * DD];
__device__ float g_k[2][BB * NN * DD];
__device__ float g_v[2][BB * NN * CC];
__device__ float g_o[2][BB * NN * CC];
__device__ float g_part[64][16][2];   // per (seg, block) LN partial (sum, sumsq)

// ---------------- helpers ----------------------------------------------------
__device__ __forceinline__ unsigned f2tf(float f) {
    unsigned u;
    asm("cvt.rna.tf32.f32 %0, %1;" : "=r"(u) : "f"(f));
    return u;
}

__device__ __forceinline__ void mma8(float* c, const unsigned* a, const unsigned* b) {
    asm volatile(
        "mma.sync.aligned.m16n8k8.row.col.f32.tf32.tf32.f32 "
        "{%0,%1,%2,%3}, {%4,%5,%6,%7}, {%8,%9}, {%0,%1,%2,%3};"
        : "+f"(c[0]), "+f"(c[1]), "+f"(c[2]), "+f"(c[3])
        : "r"(a[0]), "r"(a[1]), "r"(a[2]), "r"(a[3]), "r"(b[0]), "r"(b[1]));
}

__device__ __forceinline__ void ldsm4(unsigned* r, const unsigned* p) {
    unsigned addr = (unsigned)__cvta_generic_to_shared(p);
    asm volatile("ldmatrix.sync.aligned.m8n8.x4.shared.b16 {%0,%1,%2,%3}, [%4];"
                 : "=r"(r[0]), "=r"(r[1]), "=r"(r[2]), "=r"(r[3]) : "r"(addr));
}

__device__ __forceinline__ void ldsm2(unsigned* r, const unsigned* p) {
    unsigned addr = (unsigned)__cvta_generic_to_shared(p);
    asm volatile("ldmatrix.sync.aligned.m8n8.x2.shared.b16 {%0,%1}, [%2];"
                 : "=r"(r[0]), "=r"(r[1]) : "r"(addr));
}

__device__ __forceinline__ void cpa16(void* dst, const void* src) {
    unsigned d = (unsigned)__cvta_generic_to_shared(dst);
    asm volatile("cp.async.ca.shared.global [%0], [%1], 16;" :: "r"(d), "l"(src));
}
#define CP_COMMIT() asm volatile("cp.async.commit_group;" ::: "memory")
#define CP_WAIT(n)  asm volatile("cp.async.wait_group %0;" :: "n"(n) : "memory")

// ---------------- GEMM loaders ------------------------------------------------
// transpose path: src[k][x] -> regs. Lane owns column x = t&15, rows x+16s.
// Per LDG.32 instr: half-warp reads 16 consecutive floats (64B) -> coalesced.
__device__ __forceinline__ void ldg_kx(float v[8], const float* __restrict__ src,
                                       int ld, int k0, int x0, int t) {
    int k = t >> 4, x = t & 15;
    const float* p = src + (size_t)(k0 + k) * ld + x0 + x;
#pragma unroll
    for (int s = 0; s < 8; s++) v[s] = p[16 * s];
}
// scatter to S[x][k] k-major. Banks per STS instr: (20x + k) mod 32 -> 2-way max.
__device__ __forceinline__ void sts_kx(unsigned* S, const float v[8], int t) {
    int k = t >> 4, x = t & 15;
#pragma unroll
    for (int s = 0; s < 8; s++)
        S[(x + 16 * s) * GST + k] = __float_as_uint(v[s]);
}
// direct path: src[x][k-contig] -> S[x][k] via cp.async (128 rows x 16 floats)
__device__ __forceinline__ void cpa_xk(unsigned* S, const float* __restrict__ src,
                                       int ld, int k0, int x0, int t) {
    int x = t >> 1, off = (t & 1) * 8;
    const float* p = src + (size_t)(x0 + x) * ld + k0 + off;
    cpa16(S + x * GST + off, p);
    cpa16(S + x * GST + off + 4, p + 4);
}

// ---------------- GEMM fragment compute: 128x128 block, BK=16, ldmatrix ------
__device__ __forceinline__ void gemm_frag(const unsigned* As, const unsigned* Bs,
                                          float acc[4][4][4], int wm, int wn, int lane) {
    const int lr15 = lane & 15, lkhi = (lane >> 4) * 4;
    const int brow = (lane & 7) + ((lane & 16) ? 8 : 0);
    const int bk   = (lane & 8) ? 4 : 0;
    const unsigned* bp0 = Bs + (wn * 32 + brow) * GST + bk;
    const unsigned* bp1 = bp0 + 16 * GST;
    const unsigned* ap  = As + (wm * 64 + lr15) * GST + lkhi;
#pragma unroll
    for (int kk = 0; kk < 16; kk += 8) {
        unsigned bf0[4], bf1[4];
        ldsm4(bf0, bp0 + kk);
        ldsm4(bf1, bp1 + kk);
#pragma unroll
        for (int mt = 0; mt < 4; mt++) {
            unsigned af[4];
            ldsm4(af, ap + mt * 16 * GST + kk);
            mma8(acc[mt][0], af, bf0);
            mma8(acc[mt][1], af, bf0 + 2);
            mma8(acc[mt][2], af, bf1);
            mma8(acc[mt][3], af, bf1 + 2);
        }
    }
}

// =============================================================================
// proj_all: all six projections in ONE launch. Y[b,n,d] = sum_c X[b,c,n] W[d,c]
// =============================================================================
__global__ __launch_bounds__(256, 2)
void proj_all(const float* __restrict__ fs, const float* __restrict__ fi,
              const float* __restrict__ qs_w, const float* __restrict__ ks_w,
              const float* __restrict__ vs_w, const float* __restrict__ qi_w,
              const float* __restrict__ ki_w, const float* __restrict__ vi_w) {
    const int slot = blockIdx.y, dir = slot >> 2, s = slot & 3;
    const int b = blockIdx.z, n0 = blockIdx.x * 128;
    const float* X; const float* W; float* Y; int Dout, d0;
    if (s == 0)      { X = dir ? fs : fi; W = dir ? qs_w : qi_w; Y = g_q[dir]; Dout = DD; d0 = 0; }
    else if (s == 1) { X = dir ? fi : fs; W = dir ? ki_w : ks_w; Y = g_k[dir]; Dout = DD; d0 = 0; }
    else             { X = dir ? fi : fs; W = dir ? vi_w : vs_w; Y = g_v[dir]; Dout = CC; d0 = (s - 2) * 128; }

    __shared__ unsigned As[2][128 * GST], Bs[2][128 * GST];
    const float* Xb = X + (size_t)b * CC * NN;
    float* Yb = Y + (size_t)b * NN * Dout;
    const int t = threadIdx.x, lane = t & 31, w = t >> 5;
    const int wm = w >> 2, wn = w & 3;
    float acc[4][4][4] = {};
    float va[8];

    cpa_xk(Bs[0], W, CC, 0, d0, t);
    CP_COMMIT();
    ldg_kx(va, Xb, NN, 0, n0, t);
    sts_kx(As[0], va, t);
    CP_WAIT(0);
    __syncthreads();
    const int NIT = CC / 16;
    for (int it = 0; it < NIT; it++) {
        int buf = it & 1;
        if (it + 1 < NIT) {
            cpa_xk(Bs[buf ^ 1], W, CC, (it + 1) * 16, d0, t);
            CP_COMMIT();
            ldg_kx(va, Xb, NN, (it + 1) * 16, n0, t);
        }
        gemm_frag(As[buf], Bs[buf], acc, wm, wn, lane);
        if (it + 1 < NIT) {
            sts_kx(As[buf ^ 1], va, t);
            CP_WAIT(0);
            __syncthreads();
        }
    }
    const int r = lane >> 2, cq = lane & 3;
#pragma unroll
    for (int mt = 0; mt < 4; mt++) {
        int row = n0 + wm * 64 + mt * 16 + r;
#pragma unroll
        for (int nt = 0; nt < 4; nt++) {
            int col = d0 + wn * 32 + nt * 8 + cq * 2;
            *(float2*)(Yb + (size_t)row * Dout + col) =
                make_float2(acc[mt][nt][0], acc[mt][nt][1]);
            *(float2*)(Yb + (size_t)(row + 8) * Dout + col) =
                make_float2(acc[mt][nt][2], acc[mt][nt][3]);
        }
    }
}

// =============================================================================
// flash attention: R8-proven structure. occ-2, q-tile 64 / kv-tile 32,
// 256 threads = 8 warps (2m x 4n). Q/K ldg+cvt+sts; V cp.async raw.
// =============================================================================
#define SQS 132
#define SKS 132
#define SVS 264
#define SPS 36
#define FO_Q 0
#define FO_K 8448
#define FO_V 12672
#define FO_P 21120
#define FO_M 23424   // sm_m[2][64] double-buffered
#define FO_L 23552
#define FO_RMAX 23616
#define FO_RSUM 23872
#define FL_WORDS 24128
#define FL_BYTES (FL_WORDS * 4)

__global__ __launch_bounds__(256, 2)
void flash_kernel() {
    extern __shared__ float sm[];
    unsigned* Sq  = (unsigned*)(sm + FO_Q);   // tf32 (rounded)
    unsigned* Sk  = (unsigned*)(sm + FO_K);   // tf32 (rounded)
    unsigned* Sv  = (unsigned*)(sm + FO_V);   // raw fp32 bits via cp.async
    unsigned* Spu = (unsigned*)(sm + FO_P);   // tf32
    float* sm_m = sm + FO_M;
    float* sm_l = sm + FO_L;
    float* rmax = sm + FO_RMAX;
    float* rsum = sm + FO_RSUM;

    const int z = blockIdx.y, dir = z >> 5, b = z & 31;
    const int q0 = blockIdx.x * 64;
    const float* Qg = g_q[dir] + (size_t)b * NN * DD + (size_t)q0 * DD;
    const float* Kg = g_k[dir] + (size_t)b * NN * DD;
    const float* Vg = g_v[dir] + (size_t)b * NN * CC;
    float* Og = g_o[dir] + (size_t)b * NN * CC;

    const int t = threadIdx.x, lane = t & 31, w = t >> 5;
    const int wm = w >> 2, wn = w & 3;
    const int r = lane >> 2, cq = lane & 3;

    const int lr15 = lane & 15;
    const int lkhi = (lane >> 4) * 4;
    const int bj   = lane & 7;
    const int bk   = (lane & 8) ? 4 : 0;

    // ---- fill Sq[q][k]: 64 x 128 ----
    {
        int q = t >> 2, kg = (t & 3) * 4;
#pragma unroll
        for (int i = 0; i < 8; i++) {
            int k = kg + i * 16;
            float4 v = *(const float4*)(Qg + (size_t)q * DD + k);
            unsigned* p = Sq + q * SQS + k;
            p[0] = f2tf(v.x); p[1] = f2tf(v.y); p[2] = f2tf(v.z); p[3] = f2tf(v.w);
        }
    }
    if (t < 64) { sm_m[t] = -1e30f; sm_l[t] = 0.f; }

    float oacc[2][8][4] = {};
    const int R0 = wm * 32 + r;
    int cur = 0;

    for (int kt = 0; kt < NN / 32; kt++) {
        const int m0 = kt * 32;
        __syncthreads();   // A: prev iter done with Sk/Sv/Sp
        // ---- K tile 32x128 (ldg + cvt + sts) ----
        {
            int j = t >> 3, kg = (t & 7) * 4;
#pragma unroll
            for (int i = 0; i < 4; i++) {
                int k = kg + i * 32;
                float4 v = *(const float4*)(Kg + (size_t)(m0 + j) * DD + k);
                unsigned* p = Sk + j * SKS + k;
                p[0] = f2tf(v.x); p[1] = f2tf(v.y); p[2] = f2tf(v.z); p[3] = f2tf(v.w);
            }
        }
        // ---- V tile 32x256 via cp.async (raw fp32) — overlaps QK + softmax ----
        {
            int c4 = t & 63, mb = t >> 6;
#pragma unroll
            for (int i = 0; i < 8; i++) {
                int m = mb + i * 4;
                cpa16(Sv + m * SVS + c4 * 4, Vg + (size_t)(m0 + m) * CC + c4 * 4);
            }
            CP_COMMIT();
        }
        __syncthreads();   // B: Sk ready

        // ---- S = Q Kt : warp tile 32(q) x 8(j) ----
        float sacc[2][4] = {};
        {
            const unsigned* ap0 = Sq + (wm * 32 + lr15) * SQS + lkhi;
            const unsigned* ap1 = ap0 + 16 * SQS;
            const unsigned* bp  = Sk + (wn * 8 + bj) * SKS + bk;
#pragma unroll
            for (int kk = 0; kk < DD; kk += 8) {
                unsigned a0[4], a1[4], bf[2];
                ldsm4(a0, ap0 + kk);
                ldsm4(a1, ap1 + kk);
                ldsm2(bf, bp + kk);
                mma8(sacc[0], a0, bf);
                mma8(sacc[1], a1, bf);
            }
        }

        // ---- row-max partials ----
        {
            float pm[4];
#pragma unroll
            for (int s = 0; s < 4; s++) {
                int mt = s >> 1, h = s & 1;
                pm[s] = fmaxf(sacc[mt][h * 2], sacc[mt][h * 2 + 1]) * SCALE;
            }
#pragma unroll
            for (int o = 1; o <= 2; o <<= 1)
#pragma unroll
                for (int s = 0; s < 4; s++)
                    pm[s] = fmaxf(pm[s], __shfl_xor_sync(0xffffffffu, pm[s], o));
            if (cq == 0) {
#pragma unroll
                for (int s = 0; s < 4; s++)
                    rmax[wn * 64 + R0 + s * 8] = pm[s];
            }
        }
        __syncthreads();   // C: rmax ready

        // ---- local stats ----
        float mnv[4], cloc[4];
#pragma unroll
        for (int s = 0; s < 4; s++) {
            int row = R0 + s * 8;
            float mo = sm_m[cur * 64 + row];
            float mn = fmaxf(fmaxf(rmax[row], rmax[64 + row]),
                             fmaxf(rmax[128 + row], rmax[192 + row]));
            mn = fmaxf(mo, mn);
            mnv[s] = mn;
            cloc[s] = __expf(mo - mn);
        }
        float cl_t = 0.f;
        if (t < 64) {
            float mo = sm_m[cur * 64 + t];
            float mn_t = fmaxf(fmaxf(rmax[t], rmax[64 + t]),
                               fmaxf(rmax[128 + t], rmax[192 + t]));
            mn_t = fmaxf(mo, mn_t);
            cl_t = __expf(mo - mn_t);
            sm_m[(cur ^ 1) * 64 + t] = mn_t;
        }

        // ---- exp in registers -> Sp[q][j] tf32; sum partials ----
        {
            float psum[4];
#pragma unroll
            for (int s = 0; s < 4; s++) {
                int mt = s >> 1, h = s & 1;
                int row = wm * 32 + mt * 16 + h * 8 + r;
                float p0 = __expf(sacc[mt][h * 2]     * SCALE - mnv[s]);
                float p1 = __expf(sacc[mt][h * 2 + 1] * SCALE - mnv[s]);
                psum[s] = p0 + p1;
                int col = wn * 8 + cq * 2;
                *(uint2*)&Spu[row * SPS + col] = make_uint2(f2tf(p0), f2tf(p1));
            }
#pragma unroll
            for (int o = 1; o <= 2; o <<= 1)
#pragma unroll
                for (int s = 0; s < 4; s++)
                    psum[s] += __shfl_xor_sync(0xffffffffu, psum[s], o);
            if (cq == 0) {
#pragma unroll
                for (int s = 0; s < 4; s++)
                    rsum[wn * 64 + R0 + s * 8] = psum[s];
            }
        }
        CP_WAIT(0);
        __syncthreads();   // D: Sp, rsum, Sv ready
        if (t < 64)
            sm_l[t] = sm_l[t] * cl_t + rsum[t] + rsum[64 + t]
                      + rsum[128 + t] + rsum[192 + t];

        // ---- rescale O ----
#pragma unroll
        for (int nt = 0; nt < 8; nt++) {
            oacc[0][nt][0] *= cloc[0]; oacc[0][nt][1] *= cloc[0];
            oacc[0][nt][2] *= cloc[1]; oacc[0][nt][3] *= cloc[1];
            oacc[1][nt][0] *= cloc[2]; oacc[1][nt][1] *= cloc[2];
            oacc[1][nt][2] *= cloc[3]; oacc[1][nt][3] *= cloc[3];
        }

        // ---- O += P V : warp tile 32(q) x 64(c), K=32 ----
        {
            const unsigned* pp0 = Spu + (wm * 32 + lr15) * SPS + lkhi;
            const unsigned* pp1 = pp0 + 16 * SPS;
#pragma unroll
            for (int kk = 0; kk < 32; kk += 8) {
                unsigned a0[4], a1[4], bf[8][2];
                ldsm4(a0, pp0 + kk);
                ldsm4(a1, pp1 + kk);
#pragma unroll
                for (int nt = 0; nt < 8; nt++) {
                    int nb = wn * 64 + nt * 8;
                    bf[nt][0] = f2tf(__uint_as_float(Sv[(kk + cq) * SVS + nb + r]));
                    bf[nt][1] = f2tf(__uint_as_float(Sv[(kk + cq + 4) * SVS + nb + r]));
                }
#pragma unroll
                for (int nt = 0; nt < 8; nt++) {
                    mma8(oacc[0][nt], a0, bf[nt]);
                    mma8(oacc[1][nt], a1, bf[nt]);
                }
            }
        }
        cur ^= 1;
    }
    __syncthreads();   // sm_l final

    // ---- epilogue: O / l -> g_o ----
    {
        float i0 = 1.f / sm_l[R0];
        float i1 = 1.f / sm_l[R0 + 8];
        float i2 = 1.f / sm_l[R0 + 16];
        float i3 = 1.f / sm_l[R0 + 24];
        int row0 = q0 + R0;
#pragma unroll
        for (int nt = 0; nt < 8; nt++) {
            int col = wn * 64 + nt * 8 + cq * 2;
            *(float2*)(Og + (size_t)row0 * CC + col) =
                make_float2(oacc[0][nt][0] * i0, oacc[0][nt][1] * i0);
            *(float2*)(Og + (size_t)(row0 + 8) * CC + col) =
                make_float2(oacc[0][nt][2] * i1, oacc[0][nt][3] * i1);
            *(float2*)(Og + (size_t)(row0 + 16) * CC + col) =
                make_float2(oacc[1][nt][0] * i2, oacc[1][nt][1] * i2);
            *(float2*)(Og + (size_t)(row0 + 24) * CC + col) =
                make_float2(oacc[1][nt][2] * i3, oacc[1][nt][3] * i3);
        }
    }
}

// =============================================================================
// fuse (transposed: M = c, N = n) + fused LN partial reduction.
// =============================================================================
__global__ __launch_bounds__(256, 2)
void fuse_kernel(const float* __restrict__ fs, const float* __restrict__ fi,
                 const float* __restrict__ fw, const float* __restrict__ fbias,
                 float* __restrict__ outp) {
    __shared__ unsigned As[2][128 * GST], Bs[2][128 * GST];
    __shared__ float redS[8], redSS[8];
    const int z = blockIdx.z, dir = z >> 5, b = z & 31;
    const int n0 = blockIdx.x * 128, c0 = blockIdx.y * 128;
    const float* f = dir ? fi : fs;
    const float* fb = f + (size_t)b * CC * NN;
    const float* attb = g_o[dir] + (size_t)b * NN * CC;
    float* ob = outp + (size_t)z * CC * NN;
    const int t = threadIdx.x, lane = t & 31, w = t >> 5;
    const int wm = w >> 2, wn = w & 3;
    float acc[4][4][4] = {};
    float vb8[8];

    cpa_xk(As[0], fw, 2 * CC, 0, c0, t);
    CP_COMMIT();
    ldg_kx(vb8, fb, NN, 0, n0, t);
    sts_kx(Bs[0], vb8, t);
    CP_WAIT(0);
    __syncthreads();
    const int NIT = (2 * CC) / 16;
    for (int it = 0; it < NIT; it++) {
        int buf = it & 1;
        bool nxt_kx = false;
        if (it + 1 < NIT) {
            int k0 = (it + 1) * 16;
            cpa_xk(As[buf ^ 1], fw, 2 * CC, k0, c0, t);
            nxt_kx = (k0 < CC);
            if (nxt_kx) ldg_kx(vb8, fb, NN, k0, n0, t);
            else        cpa_xk(Bs[buf ^ 1], attb, CC, k0 - CC, n0, t);
            CP_COMMIT();
        }
        gemm_frag(As[buf], Bs[buf], acc, wm, wn, lane);
        if (it + 1 < NIT) {
            if (nxt_kx) sts_kx(Bs[buf ^ 1], vb8, t);
            CP_WAIT(0);
            __syncthreads();
        }
    }
    const int r = lane >> 2, cq = lane & 3;
    float ls = 0.f, lss = 0.f;
#pragma unroll
    for (int mt = 0; mt < 4; mt++) {
        int crow = c0 + wm * 64 + mt * 16 + r;
        float b0 = fbias[crow], b1 = fbias[crow + 8];
#pragma unroll
        for (int nt = 0; nt < 4; nt++) {
            int ncol = n0 + wn * 32 + nt * 8 + cq * 2;
            float2 r0 = *(const float2*)(fb + (size_t)crow * NN + ncol);
            float2 r1 = *(const float2*)(fb + (size_t)(crow + 8) * NN + ncol);
            float2 o0, o1;
            o0.x = fmaxf(acc[mt][nt][0] + b0, 0.f) + r0.x;
            o0.y = fmaxf(acc[mt][nt][1] + b0, 0.f) + r0.y;
            o1.x = fmaxf(acc[mt][nt][2] + b1, 0.f) + r1.x;
            o1.y = fmaxf(acc[mt][nt][3] + b1, 0.f) + r1.y;
            *(float2*)(ob + (size_t)crow * NN + ncol)       = o0;
            *(float2*)(ob + (size_t)(crow + 8) * NN + ncol) = o1;
            ls  += o0.x + o0.y + o1.x + o1.y;
            lss += o0.x * o0.x + o0.y * o0.y + o1.x * o1.x + o1.y * o1.y;
        }
    }
#pragma unroll
    for (int o = 16; o; o >>= 1) {
        ls  += __shfl_xor_sync(0xffffffffu, ls, o);
        lss += __shfl_xor_sync(0xffffffffu, lss, o);
    }
    if (lane == 0) { redS[w] = ls; redSS[w] = lss; }
    __syncthreads();
    if (t == 0) {
        float s = 0.f, ss = 0.f;
#pragma unroll
        for (int i = 0; i < 8; i++) { s += redS[i]; ss += redSS[i]; }
        int blk = blockIdx.y * 8 + blockIdx.x;
        g_part[z][blk][0] = s;
        g_part[z][blk][1] = ss;
    }
}

// =============================================================================
// ln_norm: each block recomputes its segment's stats from g_part (deterministic)
// =============================================================================
__global__ void ln_norm_kernel(float* __restrict__ outp,
                               const float* __restrict__ lnw_s, const float* __restrict__ lnb_s,
                               const float* __restrict__ lnw_i, const float* __restrict__ lnb_i) {
    const int seg = blockIdx.y, part = blockIdx.x;
    float s = 0.f, ss = 0.f;
#pragma unroll
    for (int i = 0; i < 16; i++) { s += g_part[seg][i][0]; ss += g_part[seg][i][1]; }
    const float inv_n = 1.0f / (CC * NN);
    const float mean = s * inv_n;
    const float rstd = rsqrtf(ss * inv_n - mean * mean + EPS);
    const bool isI = seg >= BB;
    const float* lw = isI ? lnw_i : lnw_s;
    const float* lb = isI ? lnb_i : lnb_s;
    float4* base = (float4*)(outp + (size_t)seg * CC * NN + part * 16384);
    for (int i = threadIdx.x; i < 4096; i += 256) {
        int c = part * 16 + (i >> 8);
        float wv = lw[c], bv = lb[c];
        float4 v = base[i];
        v.x = (v.x - mean) * rstd * wv + bv;
        v.y = (v.y - mean) * rstd * wv + bv;
        v.z = (v.z - mean) * rstd * wv + bv;
        v.w = (v.w - mean) * rstd * wv + bv;
        base[i] = v;
    }
}

// =============================================================================
extern "C" void kernel_launch(void* const* d_in, const int* in_sizes, int n_in,
                              void* d_out, int out_size) {
    const float* fs     = (const float*)d_in[0];
    const float* fi     = (const float*)d_in[1];
    const float* qs_w   = (const float*)d_in[2];
    const float* ks_w   = (const float*)d_in[3];
    const float* vs_w   = (const float*)d_in[4];
    const float* qi_w   = (const float*)d_in[5];
    const float* ki_w   = (const float*)d_in[6];
    const float* vi_w   = (const float*)d_in[7];
    const float* fuse_w = (const float*)d_in[8];
    const float* fuse_b = (const float*)d_in[9];
    const float* ln_s_w = (const float*)d_in[10];
    const float* ln_s_b = (const float*)d_in[11];
    const float* ln_i_w = (const float*)d_in[12];
    const float* ln_i_b = (const float*)d_in[13];
    float* out = (float*)d_out;

    cudaFuncSetAttribute(flash_kernel,
                         cudaFuncAttributeMaxDynamicSharedMemorySize, FL_BYTES);

    proj_all<<<dim3(8, 8, BB), 256>>>(fs, fi, qs_w, ks_w, vs_w, qi_w, ki_w, vi_w);

    flash_kernel<<<dim3(16, 64), 256, FL_BYTES>>>();

    fuse_kernel<<<dim3(8, 2, 64), 256>>>(fs, fi, fuse_w, fuse_b, out);

    ln_norm_kernel<<<dim3(16, 64), 256>>>(out, ln_s_w, ln_s_b, ln_i_w, ln_i_b);
}